// round 1
// baseline (speedup 1.0000x reference)
#include <cuda_runtime.h>

// Problem constants (from reference)
#define MAX_EDGES 3200000
#define MAX_NODES 100000
#define EPS 1e-8f

// Scratch (device globals -- no allocation allowed)
__device__ float g_w[MAX_EDGES];
__device__ float g_rowsum[MAX_NODES];

__global__ void zero_rowsum_kernel(int n_nodes) {
    int i = blockIdx.x * blockDim.x + threadIdx.x;
    if (i < n_nodes) g_rowsum[i] = 0.0f;
}

// Pass 1: per-edge score -> sigmoid -> store w, atomic add into rowsum[src]
__global__ void edge_score_kernel(const int* __restrict__ src,
                                  const int* __restrict__ dst,
                                  const float4* __restrict__ emb1,  // [N,16] = [N][4] float4
                                  const float4* __restrict__ emb2,
                                  int n_edges) {
    int e = blockIdx.x * blockDim.x + threadIdx.x;
    if (e >= n_edges) return;

    int s = src[e];
    int d = dst[e];

    const float4* a = emb1 + (size_t)s * 4;
    const float4* b = emb2 + (size_t)d * 4;

    float acc = 0.0f;
#pragma unroll
    for (int i = 0; i < 4; i++) {
        float4 av = __ldg(a + i);
        float4 bv = __ldg(b + i);
        acc = fmaf(av.x, bv.x, acc);
        acc = fmaf(av.y, bv.y, acc);
        acc = fmaf(av.z, bv.z, acc);
        acc = fmaf(av.w, bv.w, acc);
    }

    // sigmoid
    float w = __frcp_rn(1.0f + __expf(-acc));

    g_w[e] = w;
    atomicAdd(&g_rowsum[s], w);
}

// Pass 2: normalize each edge weight by its source-row sum
__global__ void normalize_kernel(const int* __restrict__ src,
                                 float* __restrict__ out,
                                 int n_edges) {
    int e = blockIdx.x * blockDim.x + threadIdx.x;
    if (e >= n_edges) return;
    float rs = g_rowsum[src[e]];
    out[e] = g_w[e] / (rs + EPS);
}

extern "C" void kernel_launch(void* const* d_in, const int* in_sizes, int n_in,
                              void* d_out, int out_size) {
    const int*    src  = (const int*)d_in[0];
    const int*    dst  = (const int*)d_in[1];
    const float4* emb1 = (const float4*)d_in[2];
    const float4* emb2 = (const float4*)d_in[3];
    float*        out  = (float*)d_out;

    int n_edges = in_sizes[0];
    int n_nodes = in_sizes[2] / 16;  // emb1 has N*16 elements

    const int T = 256;

    zero_rowsum_kernel<<<(n_nodes + T - 1) / T, T>>>(n_nodes);
    edge_score_kernel<<<(n_edges + T - 1) / T, T>>>(src, dst, emb1, emb2, n_edges);
    normalize_kernel<<<(n_edges + T - 1) / T, T>>>(src, out, n_edges);
}

// round 2
// speedup vs baseline: 1.6119x; 1.6119x over previous
#include <cuda_runtime.h>
#include <cuda_fp16.h>

#define MAX_EDGES 3200000
#define MAX_NODES 100000
#define EPS 1e-8f

// Scratch (device globals -- no allocation allowed)
__device__ float g_w[MAX_EDGES];
__device__ float g_rowsum[MAX_NODES];
__device__ __align__(16) __half g_emb1h[MAX_NODES * 16];
__device__ __align__(16) __half g_emb2h[MAX_NODES * 16];

// Prep: convert both embedding tables to fp16 (32B/row) and zero rowsum.
// Work item i in [0, 2*n4): converts one float4 -> 4 halves (8B store).
// Work item i in [2*n4, 2*n4+n_nodes): zeros rowsum.
__global__ void prep_kernel(const float4* __restrict__ emb1,
                            const float4* __restrict__ emb2,
                            int n_nodes) {
    int n4 = n_nodes * 4;
    int total = 2 * n4 + n_nodes;
    for (int i = blockIdx.x * blockDim.x + threadIdx.x; i < total;
         i += gridDim.x * blockDim.x) {
        if (i < 2 * n4) {
            float4 v = (i < n4) ? emb1[i] : emb2[i - n4];
            __half2 h0 = __floats2half2_rn(v.x, v.y);
            __half2 h1 = __floats2half2_rn(v.z, v.w);
            uint2 u = make_uint2(*(unsigned*)&h0, *(unsigned*)&h1);
            if (i < n4) ((uint2*)g_emb1h)[i] = u;
            else        ((uint2*)g_emb2h)[i - n4] = u;
        } else {
            g_rowsum[i - 2 * n4] = 0.0f;
        }
    }
}

__device__ __forceinline__ float dot8h(uint4 a, uint4 b) {
    const __half2* ah = (const __half2*)&a;
    const __half2* bh = (const __half2*)&b;
    float acc = 0.0f;
#pragma unroll
    for (int k = 0; k < 4; k++) {
        float2 fa = __half22float2(ah[k]);
        float2 fb = __half22float2(bh[k]);
        acc = fmaf(fa.x, fb.x, acc);
        acc = fmaf(fa.y, fb.y, acc);
    }
    return acc;
}

// Pass 1: 2 lanes per edge. Each lane loads one 16B half of the 32B fp16 row
// from each table, fp32-accumulates an 8-term partial dot, shfl-reduces with
// its partner, and the even lane does sigmoid + store + atomic rowsum add.
__global__ void edge_score_kernel(const int* __restrict__ src,
                                  const int* __restrict__ dst,
                                  int n_edges) {
    int tid = blockIdx.x * blockDim.x + threadIdx.x;
    int e = tid >> 1;
    int half_sel = tid & 1;
    if (e >= n_edges) return;

    int s = src[e];
    int d = dst[e];

    uint4 av = *((const uint4*)(g_emb1h + (size_t)s * 16) + half_sel);
    uint4 bv = *((const uint4*)(g_emb2h + (size_t)d * 16) + half_sel);

    float acc = dot8h(av, bv);
    acc += __shfl_xor_sync(0xffffffffu, acc, 1);

    if (half_sel == 0) {
        float w = __frcp_rn(1.0f + __expf(-acc));
        g_w[e] = w;
        atomicAdd(&g_rowsum[s], w);
    }
}

// Pass 2: normalize, 4 edges per thread (vectorized streaming loads).
__global__ void normalize_kernel(const int4* __restrict__ src4,
                                 float4* __restrict__ out4,
                                 int n_quads) {
    int i = blockIdx.x * blockDim.x + threadIdx.x;
    if (i >= n_quads) return;
    int4 s = src4[i];
    float4 w = ((const float4*)g_w)[i];
    float4 o;
    o.x = w.x / (g_rowsum[s.x] + EPS);
    o.y = w.y / (g_rowsum[s.y] + EPS);
    o.z = w.z / (g_rowsum[s.z] + EPS);
    o.w = w.w / (g_rowsum[s.w] + EPS);
    out4[i] = o;
}

// Tail (n_edges not divisible by 4)
__global__ void normalize_tail_kernel(const int* __restrict__ src,
                                      float* __restrict__ out,
                                      int start, int n_edges) {
    int e = start + blockIdx.x * blockDim.x + threadIdx.x;
    if (e >= n_edges) return;
    out[e] = g_w[e] / (g_rowsum[src[e]] + EPS);
}

extern "C" void kernel_launch(void* const* d_in, const int* in_sizes, int n_in,
                              void* d_out, int out_size) {
    const int*    src  = (const int*)d_in[0];
    const int*    dst  = (const int*)d_in[1];
    const float4* emb1 = (const float4*)d_in[2];
    const float4* emb2 = (const float4*)d_in[3];
    float*        out  = (float*)d_out;

    int n_edges = in_sizes[0];
    int n_nodes = in_sizes[2] / 16;

    const int T = 256;

    prep_kernel<<<2048, T>>>(emb1, emb2, n_nodes);

    int score_threads = 2 * n_edges;
    edge_score_kernel<<<(score_threads + T - 1) / T, T>>>(src, dst, n_edges);

    int n_quads = n_edges / 4;
    if (n_quads > 0)
        normalize_kernel<<<(n_quads + T - 1) / T, T>>>((const int4*)src,
                                                       (float4*)out, n_quads);
    int tail_start = n_quads * 4;
    int tail = n_edges - tail_start;
    if (tail > 0)
        normalize_tail_kernel<<<1, 64>>>(src, out, tail_start, n_edges);
}